// round 15
// baseline (speedup 1.0000x reference)
#include <cuda_runtime.h>
#include <cuda_fp16.h>
#include <math.h>
#include <stdint.h>

constexpr int Bn    = 2;
constexpr int Hc    = 112;
constexpr int Wc    = 112;
constexpr int CIN   = 64;
constexpr int C     = 256;
constexpr int HEADS = 8;
constexpr int HD    = 32;
constexpr int HW    = Hc * Wc;        // 12544
constexpr int M     = Bn * HW;        // 25088
constexpr int KC    = CIN * 9;        // 576

// ---------------- scratch ----------------
__device__ __align__(1024) __half  g_xqh[M * CIN];
__device__ __align__(1024) __half  g_xkvh[M * CIN];
__device__ __align__(1024) __half  g_x1[M * C];
__device__ __align__(1024) float   g_x3[M * C];
__device__ __align__(1024) __half  g_qkv[M * 3 * C];
__device__ __align__(1024) __half  g_attn[M * C];
__device__ __align__(1024) float   g_att[M * C];
__device__ __align__(1024) __half  g_atth[M * C];
__device__ __align__(1024) __half  g_mlp[M * 2 * C];
__device__ __align__(1024) float2  g_part1[2 * M];
__device__ __align__(1024) float2  g_part3[2 * M];
__device__ __align__(1024) __half  g_wt1[C * KC];      // [n][t*64+cin]
__device__ __align__(1024) __half  g_wt3[C * KC];
__device__ __align__(1024) __half  g_wqkv[3 * C * C];
__device__ __align__(1024) float   g_bqkv[3 * C];
__device__ __align__(1024) float   g_csq[3 * C];
__device__ __align__(1024) __half  g_wfc1[2 * C * C];
__device__ __align__(1024) float   g_bfc1[2 * C];
__device__ __align__(1024) float   g_csf[2 * C];
__device__ __align__(1024) __half  g_wpT[C * C];
__device__ __align__(1024) __half  g_fc2T[C * 2 * C];

// ---------------- helpers ----------------
__device__ __forceinline__ uint32_t smem_u32(const void* p) {
    return (uint32_t)__cvta_generic_to_shared(p);
}
__device__ __forceinline__ void cp16(uint32_t sdst, const void* gsrc) {
    asm volatile("cp.async.cg.shared.global [%0], [%1], 16;" :: "r"(sdst), "l"(gsrc));
}
__device__ __forceinline__ void cp16z(uint32_t sdst, const void* gsrc, int sz) {
    asm volatile("cp.async.cg.shared.global [%0], [%1], 16, %2;"
                 :: "r"(sdst), "l"(gsrc), "r"(sz));
}
__device__ __forceinline__ void cp_commit() { asm volatile("cp.async.commit_group;" ::: "memory"); }
__device__ __forceinline__ void cp_wait0()  { asm volatile("cp.async.wait_group 0;" ::: "memory"); }
__device__ __forceinline__ void cp_wait1()  { asm volatile("cp.async.wait_group 1;" ::: "memory"); }
__device__ __forceinline__ void ldsm4(uint32_t addr, uint32_t& r0, uint32_t& r1,
                                      uint32_t& r2, uint32_t& r3) {
    asm volatile("ldmatrix.sync.aligned.m8n8.x4.shared.b16 {%0,%1,%2,%3}, [%4];"
                 : "=r"(r0), "=r"(r1), "=r"(r2), "=r"(r3) : "r"(addr));
}
__device__ __forceinline__ void mma_f16(float c[4], uint32_t a0, uint32_t a1,
                                        uint32_t a2, uint32_t a3,
                                        uint32_t b0, uint32_t b1) {
    asm volatile(
        "mma.sync.aligned.m16n8k16.row.col.f32.f16.f16.f32 "
        "{%0,%1,%2,%3}, {%4,%5,%6,%7}, {%8,%9}, {%0,%1,%2,%3};"
        : "+f"(c[0]), "+f"(c[1]), "+f"(c[2]), "+f"(c[3])
        : "r"(a0), "r"(a1), "r"(a2), "r"(a3), "r"(b0), "r"(b1));
}
__device__ __forceinline__ float gelu_exact(float x) {
    return 0.5f * x * (1.0f + erff(x * 0.70710678118654752440f));
}
__device__ __forceinline__ uint32_t pack2(float a, float b) {
    __half2 h = __floats2half2_rn(a, b);
    return *reinterpret_cast<uint32_t*>(&h);
}

// ---------------------------------------------------------------------------
// Fused weight preprocessing + NHWC-half input conversion (one launch).
// ---------------------------------------------------------------------------
__global__ void prep_all(const float* __restrict__ xq, const float* __restrict__ xkv,
                         const float* __restrict__ conv1_w, const float* __restrict__ conv3_w,
                         const float* __restrict__ wp, const float* __restrict__ fc2_w,
                         const float* __restrict__ wq, const float* __restrict__ bq,
                         const float* __restrict__ wkv, const float* __restrict__ bkv,
                         const float* __restrict__ w1, const float* __restrict__ b1,
                         const float* __restrict__ w10, const float* __restrict__ b10,
                         const float* __restrict__ fc1_w, const float* __restrict__ fc1_b,
                         const float* __restrict__ w3, const float* __restrict__ b3) {
    __shared__ float red[256];
    __shared__ float tile[64][65];
    int blk = blockIdx.x;
    int i = threadIdx.x;
    if (blk < 1152) {
        if (blk < 512) {
            int n = blk & 255;
            const float* w = (blk < 256) ? conv1_w : conv3_w;
            __half* o = (blk < 256) ? g_wt1 : g_wt3;
            for (int k = i; k < KC; k += 256) {
                int cin = k / 9, t = k - cin * 9;
                o[n * KC + t * 64 + cin] = __float2half_rn(w[n * KC + k]);
            }
        }
        return;
    }
    if (blk < 1408) {
        int idx = (blk - 1152) * 256 + i;
        int n = idx >> 8, k = idx & 255;
        g_wpT[idx] = __float2half_rn(wp[k * C + n]);
        return;
    }
    if (blk < 1920) {
        int idx = (blk - 1408) * 256 + i;
        int n = idx >> 9, k = idx & 511;
        g_fc2T[idx] = __float2half_rn(fc2_w[k * C + n]);
        return;
    }
    if (blk < 2688) {
        int n = blk - 1920;
        float scale = 0.17677669529663688f;
        float w, we, bc;
        if (n < C) { w = wq[i * C + n]; we = w1[i] * w * scale; bc = b1[i] * w * scale; }
        else { int j = n - C; w = wkv[i * (2 * C) + j]; we = w10[i] * w; bc = b10[i] * w; }
        __half wh = __float2half_rn(we);
        float wr = __half2float(wh);
        g_wqkv[n * C + i] = wh;
        red[i] = bc; __syncthreads();
        for (int s = 128; s > 0; s >>= 1) { if (i < s) red[i] += red[i + s]; __syncthreads(); }
        if (i == 0) g_bqkv[n] = red[0] + (n < C ? bq[n] * scale : bkv[n - C]);
        __syncthreads();
        red[i] = wr; __syncthreads();
        for (int s = 128; s > 0; s >>= 1) { if (i < s) red[i] += red[i + s]; __syncthreads(); }
        if (i == 0) g_csq[n] = red[0];
        return;
    }
    if (blk < 3200) {
        int n = blk - 2688;
        float w = fc1_w[i * (2 * C) + n];
        __half wh = __float2half_rn(w3[i] * w);
        float wr = __half2float(wh);
        g_wfc1[n * C + i] = wh;
        red[i] = b3[i] * w; __syncthreads();
        for (int s = 128; s > 0; s >>= 1) { if (i < s) red[i] += red[i + s]; __syncthreads(); }
        if (i == 0) g_bfc1[n] = red[0] + fc1_b[n];
        __syncthreads();
        red[i] = wr; __syncthreads();
        for (int s = 128; s > 0; s >>= 1) { if (i < s) red[i] += red[i + s]; __syncthreads(); }
        if (i == 0) g_csf[n] = red[0];
        return;
    }
    {
        int tix = blk - 3200;
        const float* src;
        __half* dst;
        if (tix < 392) { src = xq; dst = g_xqh; }
        else { tix -= 392; src = xkv; dst = g_xkvh; }
        int p0 = tix * 64;
        int b = p0 / HW;
        int pp0 = p0 - b * HW;
        #pragma unroll
        for (int j = 0; j < 16; j++) {
            int idx = j * 256 + i;
            int c = idx >> 6, p = idx & 63;
            tile[c][p] = src[((size_t)(b * CIN + c)) * HW + pp0 + p];
        }
        __syncthreads();
        #pragma unroll
        for (int j = 0; j < 16; j++) {
            int idx = j * 256 + i;
            int p = idx >> 6, c = idx & 63;
            dst[(size_t)(p0 + p) * CIN + c] = __float2half_rn(tile[c][p]);
        }
    }
}

// ---------------------------------------------------------------------------
// Shared GEMM config
// ---------------------------------------------------------------------------
constexpr int GBM = 128, GBN = 128, GBK = 64;
constexpr int ASTB = GBK * 2 + 16;           // 144 bytes (padded layout)
constexpr int ASZB = GBM * ASTB;             // 18432
constexpr int BSZB = GBN * ASTB;
constexpr int STGB = ASZB + BSZB;            // 36864
constexpr int NSTG = 3;
constexpr int DYN_SMEM = NSTG * STGB;        // 110592
constexpr int OST = 132;                     // NCHW staging stride (floats)

// Warp-private-A config (K=256 GEMMs)
constexpr int RK     = 256;
constexpr int RBSTB  = RK * 2;               // 512 bytes per B row
constexpr int RBRES  = GBN * RBSTB;          // 65536
constexpr int WSTG   = 16 * 128;             // 2048 bytes per warp A stage
constexpr int DYN_SMEM_W = RBRES + 8 * 3 * WSTG;  // 114688

// Deterministic per-CTA row-stats reduction helper.
__device__ __forceinline__ void cta_row_stats(
    float* sp, int lane, int warp, float s, float q, int m_local) {
    s += __shfl_xor_sync(0xFFFFFFFFu, s, 1);
    s += __shfl_xor_sync(0xFFFFFFFFu, s, 2);
    q += __shfl_xor_sync(0xFFFFFFFFu, q, 1);
    q += __shfl_xor_sync(0xFFFFFFFFu, q, 2);
    if ((lane & 3) == 0) {
        int g = warp >> 1;
        sp[m_local * 8 + g * 2]     = s;
        sp[m_local * 8 + g * 2 + 1] = q;
    }
}

// ---------------------------------------------------------------------------
// Plain fp16 GEMM (padded 3-stage ring)
// EPI: 0 +bias | 1 +bias+res | 4 +bias+res NCHW ; OUTK: 0 fp32 | 1 half | 2 both
// STATS: emit per-CTA row stats
// ---------------------------------------------------------------------------
template <int EPI, int OUTK, int STATS, int KDIM, int NDIM>
__global__ void __launch_bounds__(256, 2)
gemmk(const __half* __restrict__ Ah, const __half* __restrict__ Bw,
      const float* __restrict__ bias, const float* __restrict__ res,
      float* __restrict__ outf, __half* __restrict__ outh,
      float2* __restrict__ part) {
    extern __shared__ char sm[];
    __shared__ float s_bias[GBN];

    int tid = threadIdx.x;
    int lane = tid & 31;
    int warp = tid >> 5;
    int bm = blockIdx.x * GBM;
    int bn = blockIdx.y * GBN;
    int wm = (warp & 1) * 64;
    int wn = (warp >> 1) * 32;

    if (tid < GBN) s_bias[tid] = bias[bn + tid];

    int p_row = tid >> 1;
    int p_ch  = (tid & 1) * 4;

    uint32_t sbase = smem_u32(sm);

    auto load_stage = [&](int stg, int k0) {
        uint32_t sA = sbase + stg * STGB;
        uint32_t sB = sA + ASZB;
        #pragma unroll
        for (int j = 0; j < 4; j++) {
            int ch = p_ch + j;
            cp16(sA + p_row * ASTB + ch * 16,
                 Ah + (size_t)(bm + p_row) * KDIM + k0 + ch * 8);
        }
        #pragma unroll
        for (int j = 0; j < 4; j++) {
            int ch = p_ch + j;
            cp16(sB + p_row * ASTB + ch * 16,
                 Bw + (size_t)(bn + p_row) * KDIM + k0 + ch * 8);
        }
    };

    uint32_t aA[4], bA[2];
    {
        int r = (lane & 7) + ((lane >> 3) & 1) * 8;
        int c16 = ((lane >> 4) & 1) * 16;
        #pragma unroll
        for (int mt = 0; mt < 4; mt++)
            aA[mt] = sbase + (wm + mt * 16 + r) * ASTB + c16;
        int rb = (lane & 7) + ((lane >> 4) & 1) * 8;
        int cb16 = ((lane >> 3) & 1) * 16;
        #pragma unroll
        for (int p = 0; p < 2; p++)
            bA[p] = sbase + ASZB + (wn + p * 16 + rb) * ASTB + cb16;
    }

    float acc[4][4][4];
    #pragma unroll
    for (int mt = 0; mt < 4; mt++)
        #pragma unroll
        for (int nt = 0; nt < 4; nt++)
            #pragma unroll
            for (int r = 0; r < 4; r++) acc[mt][nt][r] = 0.f;

    auto compute = [&](int buf) {
        uint32_t off = buf * STGB;
        #pragma unroll
        for (int kg = 0; kg < 4; kg++) {
            uint32_t a[4][4], b[2][4];
            #pragma unroll
            for (int mt = 0; mt < 4; mt++)
                ldsm4(aA[mt] + off + kg * 32, a[mt][0], a[mt][1], a[mt][2], a[mt][3]);
            #pragma unroll
            for (int p = 0; p < 2; p++)
                ldsm4(bA[p] + off + kg * 32, b[p][0], b[p][1], b[p][2], b[p][3]);
            #pragma unroll
            for (int mt = 0; mt < 4; mt++)
                #pragma unroll
                for (int p = 0; p < 2; p++) {
                    mma_f16(acc[mt][2*p],   a[mt][0], a[mt][1], a[mt][2], a[mt][3],
                            b[p][0], b[p][1]);
                    mma_f16(acc[mt][2*p+1], a[mt][0], a[mt][1], a[mt][2], a[mt][3],
                            b[p][2], b[p][3]);
                }
        }
    };

    constexpr int NIT = KDIM / GBK;
    load_stage(0, 0);
    cp_commit();
    load_stage(1, GBK);
    cp_commit();

    for (int it = 0; it < NIT; ++it) {
        if (it + 1 < NIT) cp_wait1(); else cp_wait0();
        __syncthreads();
        compute(it % NSTG);
        if (it + 2 < NIT) {
            load_stage((it + 2) % NSTG, (it + 2) * GBK);
            cp_commit();
        }
    }

    int row0 = lane >> 2;
    int col0 = (lane & 3) * 2;

    if (EPI == 4) {
        __syncthreads();
        float* so = reinterpret_cast<float*>(sm);
        #pragma unroll
        for (int mt = 0; mt < 4; mt++) {
            #pragma unroll
            for (int half_ = 0; half_ < 2; half_++) {
                int ml = wm + mt * 16 + row0 + half_ * 8;
                int m = bm + ml;
                #pragma unroll
                for (int nt = 0; nt < 4; nt++) {
                    int nl = wn + nt * 8 + col0;
                    float v0 = acc[mt][nt][half_ * 2 + 0] + s_bias[nl];
                    float v1 = acc[mt][nt][half_ * 2 + 1] + s_bias[nl + 1];
                    float2 rr = *reinterpret_cast<const float2*>(&res[(size_t)m * NDIM + bn + nl]);
                    so[nl * OST + ml]       = v0 + rr.x;
                    so[(nl + 1) * OST + ml] = v1 + rr.y;
                }
            }
        }
        __syncthreads();
        int mb = bm / HW;
        int mp0 = bm - mb * HW;
        for (int r = warp; r < GBN; r += 8) {
            const float* rowp = so + r * OST + lane * 4;
            float4 v = make_float4(rowp[0], rowp[1], rowp[2], rowp[3]);
            *reinterpret_cast<float4*>(
                &outf[((size_t)mb * C + bn + r) * HW + mp0 + lane * 4]) = v;
        }
        return;
    }

    float* sp = reinterpret_cast<float*>(sm);
    if (STATS) __syncthreads();

    #pragma unroll
    for (int mt = 0; mt < 4; mt++) {
        #pragma unroll
        for (int half_ = 0; half_ < 2; half_++) {
            int ml = wm + mt * 16 + row0 + half_ * 8;
            int m = bm + ml;
            float rsum = 0.f, rsq = 0.f;
            #pragma unroll
            for (int nt = 0; nt < 4; nt++) {
                int nl = wn + nt * 8 + col0;
                int n = bn + nl;
                float v0 = acc[mt][nt][half_ * 2 + 0] + s_bias[nl];
                float v1 = acc[mt][nt][half_ * 2 + 1] + s_bias[nl + 1];
                if (EPI == 1) {
                    float2 rr = *reinterpret_cast<const float2*>(&res[(size_t)m * NDIM + n]);
                    v0 += rr.x; v1 += rr.y;
                }
                if (STATS) { rsum += v0 + v1; rsq += v0 * v0 + v1 * v1; }
                if (OUTK == 0 || OUTK == 2)
                    *reinterpret_cast<float2*>(&outf[(size_t)m * NDIM + n]) =
                        make_float2(v0, v1);
                if (OUTK == 1 || OUTK == 2) {
                    uint32_t h = pack2(v0, v1);
                    *reinterpret_cast<uint32_t*>(&outh[(size_t)m * NDIM + n]) = h;
                }
            }
            if (STATS) cta_row_stats(sp, lane, warp, rsum, rsq, ml);
        }
    }
    if (STATS) {
        __syncthreads();
        if (tid < GBM) {
            float s = sp[tid * 8 + 0] + sp[tid * 8 + 2] + sp[tid * 8 + 4] + sp[tid * 8 + 6];
            float q = sp[tid * 8 + 1] + sp[tid * 8 + 3] + sp[tid * 8 + 5] + sp[tid * 8 + 7];
            part[(size_t)blockIdx.y * M + bm + tid] = make_float2(s, q);
        }
    }
}

// ---------------------------------------------------------------------------
// Warp-private-A B-resident GEMM (K=256): warp tile 16x128, zero mainloop
// barriers. EPI: 2 LN-affine | 3 LN-affine+GELU ; half output.
// ---------------------------------------------------------------------------
template <int EPI, int NDIM, int MGRP>
__global__ void __launch_bounds__(256, 2)
gemmw(const __half* __restrict__ Ah, const __half* __restrict__ Bw,
      const float* __restrict__ bias, const float2* __restrict__ part,
      const float* __restrict__ csum, __half* __restrict__ outh) {
    extern __shared__ char sm[];
    __shared__ float s_bias[GBN];
    __shared__ float s_csum[GBN];

    int tid = threadIdx.x;
    int lane = tid & 31;
    int warp = tid >> 5;
    int bn = blockIdx.y * GBN;
    int m0tile = blockIdx.x * MGRP;

    if (tid < GBN) {
        s_bias[tid] = bias[bn + tid];
        s_csum[tid] = csum[bn + tid];
    }

    uint32_t sbase = smem_u32(sm);

    // resident B: 128 rows x 512 B, chunk-swizzled (cooperative)
    #pragma unroll
    for (int j = 0; j < 16; j++) {
        int c = tid + j * 256;
        int row = c >> 5, ch = c & 31;
        cp16(sbase + row * RBSTB + ((ch * 16) ^ ((row & 7) << 4)),
             Bw + (size_t)(bn + row) * RK + ch * 8);
    }
    cp_commit();

    // per-warp A staging
    uint32_t aWarp = sbase + RBRES + warp * (3 * WSTG);
    int lr = lane >> 1;                  // 0..15
    int chb = (lane & 1) * 4;
    int lrx = (lr & 7) << 4;

    auto load_A = [&](int stg, int q) {
        int mt = m0tile + (q >> 2);
        int k0 = (q & 3) * 64;
        uint32_t sA = aWarp + stg * WSTG + lr * 128;
        const __half* src = Ah + (size_t)(mt * GBM + warp * 16 + lr) * RK + k0;
        #pragma unroll
        for (int j = 0; j < 4; j++) {
            int ch = chb + j;
            cp16(sA + ((ch * 16) ^ lrx), src + ch * 8);
        }
    };

    // consumer addressing
    int ar  = lane & 15;                 // a-frag row
    int axr = (ar & 7) << 4;
    int ac16 = (lane >> 4) * 16;
    uint32_t aRow = aWarp + ar * 128;
    int rb0 = (lane & 7) + ((lane >> 4) & 1) * 8;
    int bxr = (lane & 7) << 4;
    int cb16 = ((lane >> 3) & 1) * 16;
    uint32_t bRow = sbase + rb0 * RBSTB;

    float acc[16][4];
    #pragma unroll
    for (int nt = 0; nt < 16; nt++)
        #pragma unroll
        for (int r = 0; r < 4; r++) acc[nt][r] = 0.f;

    auto compute = [&](int stg, int kc) {
        uint32_t aOff = stg * WSTG;
        uint32_t bOff = kc * 128;
        #pragma unroll
        for (int kg = 0; kg < 4; kg++) {
            uint32_t a0, a1, a2, a3;
            ldsm4(aRow + aOff + ((kg * 32 + ac16) ^ axr), a0, a1, a2, a3);
            #pragma unroll
            for (int p = 0; p < 8; p++) {
                uint32_t b0, b1, b2, b3;
                ldsm4(bRow + p * 16 * RBSTB + bOff + ((kg * 32 + cb16) ^ bxr),
                      b0, b1, b2, b3);
                mma_f16(acc[2*p],     a0, a1, a2, a3, b0, b1);
                mma_f16(acc[2*p + 1], a0, a1, a2, a3, b2, b3);
            }
        }
    };

    constexpr int QTOT = MGRP * 4;
    load_A(0, 0);
    cp_commit();
    load_A(1, 1);
    cp_commit();
    cp_wait1();                  // B + A0 complete (A1 may be in flight)
    __syncthreads();             // resident B visible to all warps

    int row0 = lane >> 2;
    int col0 = (lane & 3) * 2;

    for (int q = 0; q < QTOT; ++q) {
        if (q > 0) {
            if (q + 1 < QTOT) cp_wait1(); else cp_wait0();
        }
        __syncwarp();
        if (q + 2 < QTOT) {
            load_A((q + 2) % 3, q + 2);
            cp_commit();
        }
        compute(q % 3, q & 3);
        if ((q & 3) == 3) {
            int bm = (m0tile + (q >> 2)) * GBM;
            #pragma unroll
            for (int half_ = 0; half_ < 2; half_++) {
                int m = bm + warp * 16 + row0 + half_ * 8;
                float2 p0 = part[m];
                float2 p1 = part[M + m];
                float mu = (p0.x + p1.x) * (1.0f / C);
                float rs = rsqrtf((p0.y + p1.y) * (1.0f / C) - mu * mu + 1e-5f);
                #pragma unroll
                for (int nt = 0; nt < 16; nt++) {
                    int nl = nt * 8 + col0;
                    int n = bn + nl;
                    float v0 = acc[nt][half_ * 2 + 0];
                    float v1 = acc[nt][half_ * 2 + 1];
                    v0 = rs * v0 - rs * mu * s_csum[nl] + s_bias[nl];
                    v1 = rs * v1 - rs * mu * s_csum[nl + 1] + s_bias[nl + 1];
                    if (EPI == 3) { v0 = gelu_exact(v0); v1 = gelu_exact(v1); }
                    uint32_t h = pack2(v0, v1);
                    *reinterpret_cast<uint32_t*>(&outh[(size_t)m * NDIM + n]) = h;
                    acc[nt][half_ * 2 + 0] = 0.f;
                    acc[nt][half_ * 2 + 1] = 0.f;
                }
            }
        }
    }
}

// ---------------------------------------------------------------------------
// Conv GEMM. zsel=0: conv1 -> half x1 + stats | zsel=1: conv3 -> fp32 x3
// ---------------------------------------------------------------------------
__global__ void __launch_bounds__(256, 2)
convk(const __half* __restrict__ Aq, const __half* __restrict__ Akv,
      const __half* __restrict__ W1, const __half* __restrict__ W3,
      const float* __restrict__ b1, const float* __restrict__ b3,
      __half* __restrict__ outh, float* __restrict__ outf,
      float2* __restrict__ part, int zsel) {
    extern __shared__ char sm[];
    __shared__ float s_bias[GBN];

    int z = zsel;
    const __half* Ah = z ? Akv : Aq;
    const __half* Bw = z ? W3 : W1;
    const float* bias = z ? b3 : b1;

    int tid = threadIdx.x;
    int lane = tid & 31;
    int warp = tid >> 5;
    int bm = blockIdx.x * GBM;
    int bn = blockIdx.y * GBN;
    int wm = (warp & 1) * 64;
    int wn = (warp >> 1) * 32;

    if (tid < GBN) s_bias[tid] = bias[bn + tid];

    int p_row = tid >> 1;
    int p_ch  = (tid & 1) * 4;
    int gm = bm + p_row;
    int bb = gm / HW;
    int rr0 = gm - bb * HW;
    int hh = rr0 / Wc;
    int ww = rr0 - hh * Wc;

    uint32_t sbase = smem_u32(sm);

    auto load_stage = [&](int stg, int tap) {
        uint32_t sA = sbase + stg * STGB;
        uint32_t sB = sA + ASZB;
        int dr = tap / 3 - 1, dc = tap % 3 - 1;
        int rr = hh + dr, cc = ww + dc;
        bool valid = (rr >= 0 && rr < Hc && cc >= 0 && cc < Wc);
        int sz = valid ? 16 : 0;
        const __half* srcrow = Ah +
            ((size_t)bb * HW + (valid ? rr * Wc + cc : 0)) * CIN;
        #pragma unroll
        for (int j = 0; j < 4; j++) {
            int ch = p_ch + j;
            cp16z(sA + p_row * ASTB + ch * 16, srcrow + ch * 8, sz);
        }
        #pragma unroll
        for (int j = 0; j < 4; j++) {
            int ch = p_ch + j;
            cp16(sB + p_row * ASTB + ch * 16,
                 Bw + (size_t)(bn + p_row) * KC + tap * 64 + ch * 8);
        }
    };

    uint32_t aA[4], bA[2];
    {
        int r = (lane & 7) + ((lane >> 3) & 1) * 8;
        int c16 = ((lane >> 4) & 1) * 16;
        #pragma unroll
        for (int mt = 0; mt < 4; mt++)
            aA[mt] = sbase + (wm + mt * 16 + r) * ASTB + c16;
        int rb = (lane & 7) + ((lane >> 4) & 1) * 8;
        int cb16 = ((lane >> 3) & 1) * 16;
        #pragma unroll
        for (int p = 0; p < 2; p++)
            bA[p] = sbase + ASZB + (wn + p * 16 + rb) * ASTB + cb16;
    }

    float acc[4][4][4];
    #pragma unroll
    for (int mt = 0; mt < 4; mt++)
        #pragma unroll
        for (int nt = 0; nt < 4; nt++)
            #pragma unroll
            for (int r = 0; r < 4; r++) acc[mt][nt][r] = 0.f;

    auto compute = [&](int buf) {
        uint32_t off = buf * STGB;
        #pragma unroll
        for (int kg = 0; kg < 4; kg++) {
            uint32_t a[4][4], b[2][4];
            #pragma unroll
            for (int mt = 0; mt < 4; mt++)
                ldsm4(aA[mt] + off + kg * 32, a[mt][0], a[mt][1], a[mt][2], a[mt][3]);
            #pragma unroll
            for (int p = 0; p < 2; p++)
                ldsm4(bA[p] + off + kg * 32, b[p][0], b[p][1], b[p][2], b[p][3]);
            #pragma unroll
            for (int mt = 0; mt < 4; mt++)
                #pragma unroll
                for (int p = 0; p < 2; p++) {
                    mma_f16(acc[mt][2*p],   a[mt][0], a[mt][1], a[mt][2], a[mt][3],
                            b[p][0], b[p][1]);
                    mma_f16(acc[mt][2*p+1], a[mt][0], a[mt][1], a[mt][2], a[mt][3],
                            b[p][2], b[p][3]);
                }
        }
    };

    constexpr int NIT = 9;
    load_stage(0, 0);
    cp_commit();
    load_stage(1, 1);
    cp_commit();

    for (int it = 0; it < NIT; ++it) {
        if (it + 1 < NIT) cp_wait1(); else cp_wait0();
        __syncthreads();
        compute(it % NSTG);
        if (it + 2 < NIT) {
            load_stage((it + 2) % NSTG, it + 2);
            cp_commit();
        }
    }

    int row0 = lane >> 2;
    int col0 = (lane & 3) * 2;
    float* sp = reinterpret_cast<float*>(sm);
    if (z == 0) __syncthreads();

    #pragma unroll
    for (int mt = 0; mt < 4; mt++) {
        #pragma unroll
        for (int half_ = 0; half_ < 2; half_++) {
            int ml = wm + mt * 16 + row0 + half_ * 8;
            int m = bm + ml;
            float rsum = 0.f, rsq = 0.f;
            #pragma unroll
            for (int nt = 0; nt < 4; nt++) {
                int nl = wn + nt * 8 + col0;
                int n = bn + nl;
                float v0 = acc[mt][nt][half_ * 2 + 0] + s_bias[nl];
                float v1 = acc[mt][nt][half_ * 2 + 1] + s_bias[nl + 1];
                if (z == 0) {
                    __half2 hv = __floats2half2_rn(v0, v1);
                    float2 f = __half22float2(hv);
                    rsum += f.x + f.y;
                    rsq += f.x * f.x + f.y * f.y;
                    *reinterpret_cast<uint32_t*>(&outh[(size_t)m * C + n]) =
                        *reinterpret_cast<uint32_t*>(&hv);
                } else {
                    *reinterpret_cast<float2*>(&outf[(size_t)m * C + n]) =
                        make_float2(v0, v1);
                }
            }
            if (z == 0) cta_row_stats(sp, lane, warp, rsum, rsq, ml);
        }
    }
    if (z == 0) {
        __syncthreads();
        if (tid < GBM) {
            float s = sp[tid * 8 + 0] + sp[tid * 8 + 2] + sp[tid * 8 + 4] + sp[tid * 8 + 6];
            float q = sp[tid * 8 + 1] + sp[tid * 8 + 3] + sp[tid * 8 + 5] + sp[tid * 8 + 7];
            part[(size_t)blockIdx.y * M + bm + tid] = make_float2(s, q);
        }
    }
}

// ---------------- 3x3 neighborhood attention ----------------
__global__ void __launch_bounds__(64)
nat_attn(const float* __restrict__ rpb) {
    __shared__ float ks[100 * 33];
    __shared__ float vs[100 * 33];

    int ti = blockIdx.x / 14;
    int tj = blockIdx.x % 14;
    int head = blockIdx.y;
    int b = blockIdx.z;
    int tid = threadIdx.x;
    int r0 = ti * 8 - 1;
    int c0 = tj * 8 - 1;

    for (int idx = tid; idx < 100 * 4; idx += 64) {
        int pos = idx >> 2;
        int d0 = (idx & 3) * 8;
        int rr = pos / 10, cc = pos % 10;
        int gi = r0 + rr, gj = c0 + cc;
        float kf[8] = {0,0,0,0,0,0,0,0}, vf[8] = {0,0,0,0,0,0,0,0};
        if (gi >= 0 && gi < Hc && gj >= 0 && gj < Wc) {
            size_t base = (size_t)(b * HW + gi * Wc + gj) * (3 * C) + head * HD + d0;
            uint4 ku = *reinterpret_cast<const uint4*>(g_qkv + base + C);
            uint4 vu = *reinterpret_cast<const uint4*>(g_qkv + base + 2 * C);
            const __half2* kh = reinterpret_cast<const __half2*>(&ku);
            const __half2* vh = reinterpret_cast<const __half2*>(&vu);
            #pragma unroll
            for (int v = 0; v < 4; v++) {
                float2 f = __half22float2(kh[v]);
                kf[v*2] = f.x; kf[v*2+1] = f.y;
                f = __half22float2(vh[v]);
                vf[v*2] = f.x; vf[v*2+1] = f.y;
            }
        }
        float* kp = ks + pos * 33 + d0;
        float* vp = vs + pos * 33 + d0;
        #pragma unroll
        for (int v = 0; v < 8; v++) { kp[v] = kf[v]; vp[v] = vf[v]; }
    }
    __syncthreads();

    int li = tid >> 3, lj = tid & 7;
    int i = ti * 8 + li;
    int j = tj * 8 + lj;
    int si = min(max(i - 1, 0), Hc - 3);
    int sj = min(max(j - 1, 0), Wc - 3);
    int pi = i - si;
    int pj = j - sj;
    int pbase = (si - r0) * 10 + (sj - c0);

    size_t mq = (size_t)(b * HW + i * Wc + j) * (3 * C) + head * HD;
    float q[HD];
    #pragma unroll
    for (int d = 0; d < HD; d += 8) {
        uint4 qu = *reinterpret_cast<const uint4*>(g_qkv + mq + d);
        const __half2* qh = reinterpret_cast<const __half2*>(&qu);
        #pragma unroll
        for (int v = 0; v < 4; v++) {
            float2 f = __half22float2(qh[v]);
            q[d + v*2] = f.x; q[d + v*2 + 1] = f.y;
        }
    }

    const float* rp = rpb + head * 25;
    float logits[9];
    #pragma unroll
    for (int a = 0; a < 3; a++)
        #pragma unroll
        for (int c = 0; c < 3; c++) {
            const float* kk = ks + (pbase + a * 10 + c) * 33;
            float s = 0.f;
            #pragma unroll
            for (int d = 0; d < HD; d++) s += q[d] * kk[d];
            logits[a * 3 + c] = s + rp[(a - pi + 2) * 5 + (c - pj + 2)];
        }

    float mx = logits[0];
    #pragma unroll
    for (int n = 1; n < 9; n++) mx = fmaxf(mx, logits[n]);
    float wsum = 0.f, wgt[9];
    #pragma unroll
    for (int n = 0; n < 9; n++) { wgt[n] = expf(logits[n] - mx); wsum += wgt[n]; }
    float inv = 1.0f / wsum;

    float o[HD];
    #pragma unroll
    for (int d = 0; d < HD; d++) o[d] = 0.f;
    #pragma unroll
    for (int n = 0; n < 9; n++) {
        float wn = wgt[n] * inv;
        const float* vv = vs + (pbase + (n / 3) * 10 + (n % 3)) * 33;
        #pragma unroll
        for (int d = 0; d < HD; d++) o[d] += wn * vv[d];
    }

    size_t mo = (size_t)(b * HW + i * Wc + j) * C + head * HD;
    #pragma unroll
    for (int d = 0; d < HD; d += 8) {
        uint4 u;
        u.x = pack2(o[d+0], o[d+1]);
        u.y = pack2(o[d+2], o[d+3]);
        u.z = pack2(o[d+4], o[d+5]);
        u.w = pack2(o[d+6], o[d+7]);
        *reinterpret_cast<uint4*>(g_attn + mo + d) = u;
    }
}

// ---------------- launch ----------------
extern "C" void kernel_launch(void* const* d_in, const int* in_sizes, int n_in,
                              void* d_out, int out_size) {
    const float* xq      = (const float*)d_in[0];
    const float* xkv     = (const float*)d_in[1];
    const float* conv1_w = (const float*)d_in[2];
    const float* conv1_b = (const float*)d_in[3];
    const float* conv3_w = (const float*)d_in[4];
    const float* conv3_b = (const float*)d_in[5];
    const float* ln1_w   = (const float*)d_in[6];
    const float* ln1_b   = (const float*)d_in[7];
    const float* ln10_w  = (const float*)d_in[8];
    const float* ln10_b  = (const float*)d_in[9];
    const float* ln3_w   = (const float*)d_in[10];
    const float* ln3_b   = (const float*)d_in[11];
    const float* wq      = (const float*)d_in[12];
    const float* bq      = (const float*)d_in[13];
    const float* wkv     = (const float*)d_in[14];
    const float* bkv     = (const float*)d_in[15];
    const float* rpb     = (const float*)d_in[16];
    const float* wp      = (const float*)d_in[17];
    const float* bp      = (const float*)d_in[18];
    const float* fc1_w   = (const float*)d_in[19];
    const float* fc1_b   = (const float*)d_in[20];
    const float* fc2_w   = (const float*)d_in[21];
    const float* fc2_b   = (const float*)d_in[22];
    float* out = (float*)d_out;

    float *p_x3, *p_att, *p_bqkv, *p_csq, *p_bfc1, *p_csf;
    float2 *p_part1, *p_part3;
    __half *p_xqh, *p_xkvh, *p_x1, *p_qkv, *p_attn, *p_atth, *p_mlp,
           *p_wt1, *p_wt3, *p_wqkv, *p_wfc1, *p_wpT, *p_fc2T;
    cudaGetSymbolAddress((void**)&p_xqh, g_xqh);
    cudaGetSymbolAddress((void**)&p_xkvh, g_xkvh);
    cudaGetSymbolAddress((void**)&p_x1, g_x1);
    cudaGetSymbolAddress((void**)&p_x3, g_x3);
    cudaGetSymbolAddress((void**)&p_qkv, g_qkv);
    cudaGetSymbolAddress((void**)&p_attn, g_attn);
    cudaGetSymbolAddress((void**)&p_att, g_att);
    cudaGetSymbolAddress((void**)&p_atth, g_atth);
    cudaGetSymbolAddress((void**)&p_mlp, g_mlp);
    cudaGetSymbolAddress((void**)&p_part1, g_part1);
    cudaGetSymbolAddress((void**)&p_part3, g_part3);
    cudaGetSymbolAddress((void**)&p_wt1, g_wt1);
    cudaGetSymbolAddress((void**)&p_wt3, g_wt3);
    cudaGetSymbolAddress((void**)&p_wqkv, g_wqkv);
    cudaGetSymbolAddress((void**)&p_bqkv, g_bqkv);
    cudaGetSymbolAddress((void**)&p_csq, g_csq);
    cudaGetSymbolAddress((void**)&p_wfc1, g_wfc1);
    cudaGetSymbolAddress((void**)&p_bfc1, g_bfc1);
    cudaGetSymbolAddress((void**)&p_csf, g_csf);
    cudaGetSymbolAddress((void**)&p_wpT, g_wpT);
    cudaGetSymbolAddress((void**)&p_fc2T, g_fc2T);

    cudaFuncSetAttribute(convk,                cudaFuncAttributeMaxDynamicSharedMemorySize, DYN_SMEM);
    cudaFuncSetAttribute(gemmw<2,3*C,4>,       cudaFuncAttributeMaxDynamicSharedMemorySize, DYN_SMEM_W);
    cudaFuncSetAttribute(gemmw<3,2*C,2>,       cudaFuncAttributeMaxDynamicSharedMemorySize, DYN_SMEM_W);
    cudaFuncSetAttribute(gemmk<1,2,1,C,C>,     cudaFuncAttributeMaxDynamicSharedMemorySize, DYN_SMEM);
    cudaFuncSetAttribute(gemmk<4,0,0,2*C,C>,   cudaFuncAttributeMaxDynamicSharedMemorySize, DYN_SMEM);

    static cudaStream_t s2 = nullptr;
    static cudaEvent_t evP = nullptr, ev3 = nullptr;
    if (s2 == nullptr) {
        cudaStreamCreateWithFlags(&s2, cudaStreamNonBlocking);
        cudaEventCreateWithFlags(&evP, cudaEventDisableTiming);
        cudaEventCreateWithFlags(&ev3, cudaEventDisableTiming);
    }

    // 1. weight prep + NHWC conversion
    prep_all<<<3984, 256>>>(xq, xkv, conv1_w, conv3_w, wp, fc2_w,
                            wq, bq, wkv, bkv, ln1_w, ln1_b, ln10_w, ln10_b,
                            fc1_w, fc1_b, ln3_w, ln3_b);
    cudaEventRecord(evP, 0);

    // fork: conv3 on side stream
    cudaStreamWaitEvent(s2, evP, 0);
    convk<<<dim3(M / GBM, C / GBN), 256, DYN_SMEM, s2>>>(
        p_xqh, p_xkvh, p_wt1, p_wt3, conv1_b, conv3_b, p_x1, p_x3, p_part1, 1);
    cudaEventRecord(ev3, s2);

    // 2. conv1 (+ LN1 stats in epilogue)
    convk<<<dim3(M / GBM, C / GBN), 256, DYN_SMEM>>>(
        p_xqh, p_xkvh, p_wt1, p_wt3, conv1_b, conv3_b, p_x1, p_x3, p_part1, 0);

    // 3. qkv projection: barrier-free warp-private-A GEMM
    gemmw<2,3*C,4><<<dim3(M / GBM / 4, (3 * C) / GBN), 256, DYN_SMEM_W>>>(
        p_x1, p_wqkv, p_bqkv, p_part1, p_csq, p_qkv);

    // 4. neighborhood attention
    nat_attn<<<dim3(14 * 14, HEADS, Bn), 64>>>(rpb);

    // join: proj needs x3
    cudaStreamWaitEvent(0, ev3, 0);

    // 5. proj + x3 residual (+ LN3 stats in epilogue)
    gemmk<1,2,1,C,C><<<dim3(M / GBM, C / GBN), 256, DYN_SMEM>>>(
        p_attn, p_wpT, bp, p_x3, p_att, p_atth, p_part3);

    // 6. fc1: barrier-free warp-private-A GEMM + LN + GELU
    gemmw<3,2*C,2><<<dim3(M / GBM / 2, (2 * C) / GBN), 256, DYN_SMEM_W>>>(
        p_atth, p_wfc1, p_bfc1, p_part3, p_csf, p_mlp);

    // 7. fc2 + att residual, coalesced NCHW store
    gemmk<4,0,0,2*C,C><<<dim3(M / GBM, C / GBN), 256, DYN_SMEM>>>(
        p_mlp, p_fc2T, fc2_b, p_att, out, nullptr, nullptr);
}

// round 16
// speedup vs baseline: 1.0149x; 1.0149x over previous
#include <cuda_runtime.h>
#include <cuda_fp16.h>
#include <math.h>
#include <stdint.h>

constexpr int Bn    = 2;
constexpr int Hc    = 112;
constexpr int Wc    = 112;
constexpr int CIN   = 64;
constexpr int C     = 256;
constexpr int HEADS = 8;
constexpr int HD    = 32;
constexpr int HW    = Hc * Wc;        // 12544
constexpr int M     = Bn * HW;        // 25088
constexpr int KC    = CIN * 9;        // 576

// ---------------- scratch ----------------
__device__ __align__(1024) __half  g_xqh[M * CIN];
__device__ __align__(1024) __half  g_xkvh[M * CIN];
__device__ __align__(1024) __half  g_x1[M * C];
__device__ __align__(1024) float   g_x3[M * C];
__device__ __align__(1024) __half  g_qkv[M * 3 * C];
__device__ __align__(1024) __half  g_attn[M * C];
__device__ __align__(1024) float   g_att[M * C];
__device__ __align__(1024) __half  g_atth[M * C];
__device__ __align__(1024) __half  g_mlp[M * 2 * C];
__device__ __align__(1024) float2  g_part1[2 * M];
__device__ __align__(1024) float2  g_part3[2 * M];
__device__ __align__(1024) __half  g_wt1[C * KC];      // [n][t*64+cin]
__device__ __align__(1024) __half  g_wt3[C * KC];
__device__ __align__(1024) __half  g_wqkv[3 * C * C];
__device__ __align__(1024) float   g_bqkv[3 * C];
__device__ __align__(1024) float   g_csq[3 * C];
__device__ __align__(1024) __half  g_wfc1[2 * C * C];
__device__ __align__(1024) float   g_bfc1[2 * C];
__device__ __align__(1024) float   g_csf[2 * C];
__device__ __align__(1024) __half  g_wpT[C * C];
__device__ __align__(1024) __half  g_fc2T[C * 2 * C];

// ---------------- helpers ----------------
__device__ __forceinline__ uint32_t smem_u32(const void* p) {
    return (uint32_t)__cvta_generic_to_shared(p);
}
__device__ __forceinline__ void cp16(uint32_t sdst, const void* gsrc) {
    asm volatile("cp.async.cg.shared.global [%0], [%1], 16;" :: "r"(sdst), "l"(gsrc));
}
__device__ __forceinline__ void cp16z(uint32_t sdst, const void* gsrc, int sz) {
    asm volatile("cp.async.cg.shared.global [%0], [%1], 16, %2;"
                 :: "r"(sdst), "l"(gsrc), "r"(sz));
}
__device__ __forceinline__ void cp_commit() { asm volatile("cp.async.commit_group;" ::: "memory"); }
__device__ __forceinline__ void cp_wait0()  { asm volatile("cp.async.wait_group 0;" ::: "memory"); }
__device__ __forceinline__ void cp_wait1()  { asm volatile("cp.async.wait_group 1;" ::: "memory"); }
__device__ __forceinline__ void ldsm4(uint32_t addr, uint32_t& r0, uint32_t& r1,
                                      uint32_t& r2, uint32_t& r3) {
    asm volatile("ldmatrix.sync.aligned.m8n8.x4.shared.b16 {%0,%1,%2,%3}, [%4];"
                 : "=r"(r0), "=r"(r1), "=r"(r2), "=r"(r3) : "r"(addr));
}
__device__ __forceinline__ void mma_f16(float c[4], uint32_t a0, uint32_t a1,
                                        uint32_t a2, uint32_t a3,
                                        uint32_t b0, uint32_t b1) {
    asm volatile(
        "mma.sync.aligned.m16n8k16.row.col.f32.f16.f16.f32 "
        "{%0,%1,%2,%3}, {%4,%5,%6,%7}, {%8,%9}, {%0,%1,%2,%3};"
        : "+f"(c[0]), "+f"(c[1]), "+f"(c[2]), "+f"(c[3])
        : "r"(a0), "r"(a1), "r"(a2), "r"(a3), "r"(b0), "r"(b1));
}
__device__ __forceinline__ float gelu_exact(float x) {
    return 0.5f * x * (1.0f + erff(x * 0.70710678118654752440f));
}
__device__ __forceinline__ uint32_t pack2(float a, float b) {
    __half2 h = __floats2half2_rn(a, b);
    return *reinterpret_cast<uint32_t*>(&h);
}

// ---------------------------------------------------------------------------
// Critical-path preprocessing: conv weights, qkv fold, NHWC conversion.
// Blocks: [0,512) convw | [512,1280) qkv fold | [1280,2064) NHWC
// ---------------------------------------------------------------------------
__global__ void prep_crit(const float* __restrict__ xq, const float* __restrict__ xkv,
                          const float* __restrict__ conv1_w, const float* __restrict__ conv3_w,
                          const float* __restrict__ wq, const float* __restrict__ bq,
                          const float* __restrict__ wkv, const float* __restrict__ bkv,
                          const float* __restrict__ w1, const float* __restrict__ b1,
                          const float* __restrict__ w10, const float* __restrict__ b10) {
    __shared__ float red[256];
    __shared__ float tile[64][65];
    int blk = blockIdx.x;
    int i = threadIdx.x;
    if (blk < 512) {
        int n = blk & 255;
        const float* w = (blk < 256) ? conv1_w : conv3_w;
        __half* o = (blk < 256) ? g_wt1 : g_wt3;
        for (int k = i; k < KC; k += 256) {
            int cin = k / 9, t = k - cin * 9;
            o[n * KC + t * 64 + cin] = __float2half_rn(w[n * KC + k]);
        }
        return;
    }
    if (blk < 1280) {
        int n = blk - 512;                       // 0..767
        float scale = 0.17677669529663688f;
        float w, we, bc;
        if (n < C) { w = wq[i * C + n]; we = w1[i] * w * scale; bc = b1[i] * w * scale; }
        else { int j = n - C; w = wkv[i * (2 * C) + j]; we = w10[i] * w; bc = b10[i] * w; }
        __half wh = __float2half_rn(we);
        float wr = __half2float(wh);
        g_wqkv[n * C + i] = wh;
        red[i] = bc; __syncthreads();
        for (int s = 128; s > 0; s >>= 1) { if (i < s) red[i] += red[i + s]; __syncthreads(); }
        if (i == 0) g_bqkv[n] = red[0] + (n < C ? bq[n] * scale : bkv[n - C]);
        __syncthreads();
        red[i] = wr; __syncthreads();
        for (int s = 128; s > 0; s >>= 1) { if (i < s) red[i] += red[i + s]; __syncthreads(); }
        if (i == 0) g_csq[n] = red[0];
        return;
    }
    {
        int tix = blk - 1280;                    // 0..783
        const float* src;
        __half* dst;
        if (tix < 392) { src = xq; dst = g_xqh; }
        else { tix -= 392; src = xkv; dst = g_xkvh; }
        int p0 = tix * 64;
        int b = p0 / HW;
        int pp0 = p0 - b * HW;
        #pragma unroll
        for (int j = 0; j < 16; j++) {
            int idx = j * 256 + i;
            int c = idx >> 6, p = idx & 63;
            tile[c][p] = src[((size_t)(b * CIN + c)) * HW + pp0 + p];
        }
        __syncthreads();
        #pragma unroll
        for (int j = 0; j < 16; j++) {
            int idx = j * 256 + i;
            int p = idx >> 6, c = idx & 63;
            dst[(size_t)(p0 + p) * CIN + c] = __float2half_rn(tile[c][p]);
        }
    }
}

// ---------------------------------------------------------------------------
// Late preprocessing (overlapped on side stream): wpT, fc2T, fc1 fold.
// Blocks: [0,256) wpT | [256,768) fc2T | [768,1280) fc1 fold
// ---------------------------------------------------------------------------
__global__ void prep_late(const float* __restrict__ wp, const float* __restrict__ fc2_w,
                          const float* __restrict__ fc1_w, const float* __restrict__ fc1_b,
                          const float* __restrict__ w3, const float* __restrict__ b3) {
    __shared__ float red[256];
    int blk = blockIdx.x;
    int i = threadIdx.x;
    if (blk < 256) {
        int idx = blk * 256 + i;
        int n = idx >> 8, k = idx & 255;
        g_wpT[idx] = __float2half_rn(wp[k * C + n]);
        return;
    }
    if (blk < 768) {
        int idx = (blk - 256) * 256 + i;
        int n = idx >> 9, k = idx & 511;
        g_fc2T[idx] = __float2half_rn(fc2_w[k * C + n]);
        return;
    }
    {
        int n = blk - 768;                       // 0..511
        float w = fc1_w[i * (2 * C) + n];
        __half wh = __float2half_rn(w3[i] * w);
        float wr = __half2float(wh);
        g_wfc1[n * C + i] = wh;
        red[i] = b3[i] * w; __syncthreads();
        for (int s = 128; s > 0; s >>= 1) { if (i < s) red[i] += red[i + s]; __syncthreads(); }
        if (i == 0) g_bfc1[n] = red[0] + fc1_b[n];
        __syncthreads();
        red[i] = wr; __syncthreads();
        for (int s = 128; s > 0; s >>= 1) { if (i < s) red[i] += red[i + s]; __syncthreads(); }
        if (i == 0) g_csf[n] = red[0];
    }
}

// ---------------------------------------------------------------------------
// Shared GEMM config
// ---------------------------------------------------------------------------
constexpr int GBM = 128, GBN = 128, GBK = 64;
constexpr int ASTB = GBK * 2 + 16;           // 144 bytes (padded layout)
constexpr int ASZB = GBM * ASTB;             // 18432
constexpr int BSZB = GBN * ASTB;
constexpr int STGB = ASZB + BSZB;            // 36864
constexpr int NSTG = 3;
constexpr int DYN_SMEM = NSTG * STGB;        // 110592
constexpr int OST = 132;                     // NCHW staging stride (floats)

// B-resident swizzled config (K=256 GEMMs)
constexpr int RK     = 256;
constexpr int RBSTB  = RK * 2;               // 512 bytes per B row
constexpr int RBRES  = GBN * RBSTB;          // 65536
constexpr int RASTG  = GBM * 128;            // 16384 per swizzled A stage
constexpr int DYN_SMEM_R = RBRES + 3 * RASTG; // 114688

// Deterministic per-CTA row-stats reduction helper.
__device__ __forceinline__ void cta_row_stats(
    float* sp, int lane, int warp, float s, float q, int m_local) {
    s += __shfl_xor_sync(0xFFFFFFFFu, s, 1);
    s += __shfl_xor_sync(0xFFFFFFFFu, s, 2);
    q += __shfl_xor_sync(0xFFFFFFFFu, q, 1);
    q += __shfl_xor_sync(0xFFFFFFFFu, q, 2);
    if ((lane & 3) == 0) {
        int g = warp >> 1;
        sp[m_local * 8 + g * 2]     = s;
        sp[m_local * 8 + g * 2 + 1] = q;
    }
}

// ---------------------------------------------------------------------------
// Plain fp16 GEMM (padded 3-stage ring)
// EPI: 0 +bias | 1 +bias+res | 4 +bias+res NCHW ; OUTK: 0 fp32 | 1 half | 2 both
// STATS: emit per-CTA row stats
// ---------------------------------------------------------------------------
template <int EPI, int OUTK, int STATS, int KDIM, int NDIM>
__global__ void __launch_bounds__(256, 2)
gemmk(const __half* __restrict__ Ah, const __half* __restrict__ Bw,
      const float* __restrict__ bias, const float* __restrict__ res,
      float* __restrict__ outf, __half* __restrict__ outh,
      float2* __restrict__ part) {
    extern __shared__ char sm[];
    __shared__ float s_bias[GBN];

    int tid = threadIdx.x;
    int lane = tid & 31;
    int warp = tid >> 5;
    int bm = blockIdx.x * GBM;
    int bn = blockIdx.y * GBN;
    int wm = (warp & 1) * 64;
    int wn = (warp >> 1) * 32;

    if (tid < GBN) s_bias[tid] = bias[bn + tid];

    int p_row = tid >> 1;
    int p_ch  = (tid & 1) * 4;

    uint32_t sbase = smem_u32(sm);

    auto load_stage = [&](int stg, int k0) {
        uint32_t sA = sbase + stg * STGB;
        uint32_t sB = sA + ASZB;
        #pragma unroll
        for (int j = 0; j < 4; j++) {
            int ch = p_ch + j;
            cp16(sA + p_row * ASTB + ch * 16,
                 Ah + (size_t)(bm + p_row) * KDIM + k0 + ch * 8);
        }
        #pragma unroll
        for (int j = 0; j < 4; j++) {
            int ch = p_ch + j;
            cp16(sB + p_row * ASTB + ch * 16,
                 Bw + (size_t)(bn + p_row) * KDIM + k0 + ch * 8);
        }
    };

    uint32_t aA[4], bA[2];
    {
        int r = (lane & 7) + ((lane >> 3) & 1) * 8;
        int c16 = ((lane >> 4) & 1) * 16;
        #pragma unroll
        for (int mt = 0; mt < 4; mt++)
            aA[mt] = sbase + (wm + mt * 16 + r) * ASTB + c16;
        int rb = (lane & 7) + ((lane >> 4) & 1) * 8;
        int cb16 = ((lane >> 3) & 1) * 16;
        #pragma unroll
        for (int p = 0; p < 2; p++)
            bA[p] = sbase + ASZB + (wn + p * 16 + rb) * ASTB + cb16;
    }

    float acc[4][4][4];
    #pragma unroll
    for (int mt = 0; mt < 4; mt++)
        #pragma unroll
        for (int nt = 0; nt < 4; nt++)
            #pragma unroll
            for (int r = 0; r < 4; r++) acc[mt][nt][r] = 0.f;

    auto compute = [&](int buf) {
        uint32_t off = buf * STGB;
        #pragma unroll
        for (int kg = 0; kg < 4; kg++) {
            uint32_t a[4][4], b[2][4];
            #pragma unroll
            for (int mt = 0; mt < 4; mt++)
                ldsm4(aA[mt] + off + kg * 32, a[mt][0], a[mt][1], a[mt][2], a[mt][3]);
            #pragma unroll
            for (int p = 0; p < 2; p++)
                ldsm4(bA[p] + off + kg * 32, b[p][0], b[p][1], b[p][2], b[p][3]);
            #pragma unroll
            for (int mt = 0; mt < 4; mt++)
                #pragma unroll
                for (int p = 0; p < 2; p++) {
                    mma_f16(acc[mt][2*p],   a[mt][0], a[mt][1], a[mt][2], a[mt][3],
                            b[p][0], b[p][1]);
                    mma_f16(acc[mt][2*p+1], a[mt][0], a[mt][1], a[mt][2], a[mt][3],
                            b[p][2], b[p][3]);
                }
        }
    };

    constexpr int NIT = KDIM / GBK;
    load_stage(0, 0);
    cp_commit();
    load_stage(1, GBK);
    cp_commit();

    for (int it = 0; it < NIT; ++it) {
        if (it + 1 < NIT) cp_wait1(); else cp_wait0();
        __syncthreads();
        compute(it % NSTG);
        if (it + 2 < NIT) {
            load_stage((it + 2) % NSTG, (it + 2) * GBK);
            cp_commit();
        }
    }

    int row0 = lane >> 2;
    int col0 = (lane & 3) * 2;

    if (EPI == 4) {
        __syncthreads();
        float* so = reinterpret_cast<float*>(sm);
        #pragma unroll
        for (int mt = 0; mt < 4; mt++) {
            #pragma unroll
            for (int half_ = 0; half_ < 2; half_++) {
                int ml = wm + mt * 16 + row0 + half_ * 8;
                int m = bm + ml;
                #pragma unroll
                for (int nt = 0; nt < 4; nt++) {
                    int nl = wn + nt * 8 + col0;
                    float v0 = acc[mt][nt][half_ * 2 + 0] + s_bias[nl];
                    float v1 = acc[mt][nt][half_ * 2 + 1] + s_bias[nl + 1];
                    float2 rr = *reinterpret_cast<const float2*>(&res[(size_t)m * NDIM + bn + nl]);
                    so[nl * OST + ml]       = v0 + rr.x;
                    so[(nl + 1) * OST + ml] = v1 + rr.y;
                }
            }
        }
        __syncthreads();
        int mb = bm / HW;
        int mp0 = bm - mb * HW;
        for (int r = warp; r < GBN; r += 8) {
            const float* rowp = so + r * OST + lane * 4;
            float4 v = make_float4(rowp[0], rowp[1], rowp[2], rowp[3]);
            *reinterpret_cast<float4*>(
                &outf[((size_t)mb * C + bn + r) * HW + mp0 + lane * 4]) = v;
        }
        return;
    }

    float* sp = reinterpret_cast<float*>(sm);
    if (STATS) __syncthreads();

    #pragma unroll
    for (int mt = 0; mt < 4; mt++) {
        #pragma unroll
        for (int half_ = 0; half_ < 2; half_++) {
            int ml = wm + mt * 16 + row0 + half_ * 8;
            int m = bm + ml;
            float rsum = 0.f, rsq = 0.f;
            #pragma unroll
            for (int nt = 0; nt < 4; nt++) {
                int nl = wn + nt * 8 + col0;
                int n = bn + nl;
                float v0 = acc[mt][nt][half_ * 2 + 0] + s_bias[nl];
                float v1 = acc[mt][nt][half_ * 2 + 1] + s_bias[nl + 1];
                if (EPI == 1) {
                    float2 rr = *reinterpret_cast<const float2*>(&res[(size_t)m * NDIM + n]);
                    v0 += rr.x; v1 += rr.y;
                }
                if (STATS) { rsum += v0 + v1; rsq += v0 * v0 + v1 * v1; }
                if (OUTK == 0 || OUTK == 2)
                    *reinterpret_cast<float2*>(&outf[(size_t)m * NDIM + n]) =
                        make_float2(v0, v1);
                if (OUTK == 1 || OUTK == 2) {
                    uint32_t h = pack2(v0, v1);
                    *reinterpret_cast<uint32_t*>(&outh[(size_t)m * NDIM + n]) = h;
                }
            }
            if (STATS) cta_row_stats(sp, lane, warp, rsum, rsq, ml);
        }
    }
    if (STATS) {
        __syncthreads();
        if (tid < GBM) {
            float s = sp[tid * 8 + 0] + sp[tid * 8 + 2] + sp[tid * 8 + 4] + sp[tid * 8 + 6];
            float q = sp[tid * 8 + 1] + sp[tid * 8 + 3] + sp[tid * 8 + 5] + sp[tid * 8 + 7];
            part[(size_t)blockIdx.y * M + bm + tid] = make_float2(s, q);
        }
    }
}

// ---------------------------------------------------------------------------
// B-resident m-grouped GEMM (K=256), swizzled layouts, 3-stage A ring,
// ONE __syncthreads per q-iter. (R14 configuration — best known.)
// EPI: 2 LN-affine | 3 LN-affine+GELU ; LN stats combined from part[]
// ---------------------------------------------------------------------------
template <int EPI, int OUTK, int NDIM, int MGRP>
__global__ void __launch_bounds__(256, 2)
gemmr(const __half* __restrict__ Ah, const __half* __restrict__ Bw,
      const float* __restrict__ bias, const float2* __restrict__ part,
      const float* __restrict__ csum,
      float* __restrict__ outf, __half* __restrict__ outh) {
    extern __shared__ char sm[];
    __shared__ float s_bias[GBN];
    __shared__ float s_csum[GBN];

    int tid = threadIdx.x;
    int lane = tid & 31;
    int warp = tid >> 5;
    int bn = blockIdx.y * GBN;
    int m0tile = blockIdx.x * MGRP;
    int wm = (warp & 1) * 64;
    int wn = (warp >> 1) * 32;

    if (tid < GBN) {
        s_bias[tid] = bias[bn + tid];
        s_csum[tid] = csum[bn + tid];
    }

    int p_row = tid >> 1;
    int p_ch  = (tid & 1) * 4;
    int p_xr  = (p_row & 7) << 4;
    uint32_t sbase = smem_u32(sm);

    // resident B: 128 rows x 512 B, chunk-swizzled
    #pragma unroll
    for (int j = 0; j < 16; j++) {
        int c = tid + j * 256;
        int row = c >> 5, ch = c & 31;
        cp16(sbase + row * RBSTB + ((ch * 16) ^ ((row & 7) << 4)),
             Bw + (size_t)(bn + row) * RK + ch * 8);
    }
    cp_commit();

    auto load_A = [&](int stg, int q) {
        int mt = m0tile + (q >> 2);
        int k0 = (q & 3) * 64;
        uint32_t sA = sbase + RBRES + stg * RASTG + p_row * 128;
        const __half* src = Ah + (size_t)(mt * GBM + p_row) * RK + k0;
        #pragma unroll
        for (int j = 0; j < 4; j++) {
            int ch = p_ch + j;
            cp16(sA + ((ch * 16) ^ p_xr), src + ch * 8);
        }
    };

    // consumer frag bases
    int c16 = ((lane >> 4) & 1) * 16;
    uint32_t aBase[4];
    int aXr[4];
    {
        int r0 = (lane & 7) + ((lane >> 3) & 1) * 8;
        #pragma unroll
        for (int mt = 0; mt < 4; mt++) {
            int r = wm + mt * 16 + r0;
            aBase[mt] = sbase + RBRES + r * 128;
            aXr[mt] = (r & 7) << 4;
        }
    }
    int cb16 = ((lane >> 3) & 1) * 16;
    uint32_t bBase[2];
    int bXr[2];
    {
        int rb0 = ((lane >> 4) & 1) * 8 + (lane & 7);
        #pragma unroll
        for (int p = 0; p < 2; p++) {
            int r = wn + p * 16 + rb0;
            bBase[p] = sbase + r * RBSTB;
            bXr[p] = (r & 7) << 4;
        }
    }

    float acc[4][4][4];
    #pragma unroll
    for (int mt = 0; mt < 4; mt++)
        #pragma unroll
        for (int nt = 0; nt < 4; nt++)
            #pragma unroll
            for (int r = 0; r < 4; r++) acc[mt][nt][r] = 0.f;

    auto compute = [&](int stg, int kc) {
        uint32_t offA = stg * RASTG;
        uint32_t offB = kc * 128;
        #pragma unroll
        for (int kg = 0; kg < 4; kg++) {
            uint32_t a[4][4], b[2][4];
            #pragma unroll
            for (int mt = 0; mt < 4; mt++)
                ldsm4(aBase[mt] + offA + ((kg * 32 + c16) ^ aXr[mt]),
                      a[mt][0], a[mt][1], a[mt][2], a[mt][3]);
            #pragma unroll
            for (int p = 0; p < 2; p++)
                ldsm4(bBase[p] + offB + ((kg * 32 + cb16) ^ bXr[p]),
                      b[p][0], b[p][1], b[p][2], b[p][3]);
            #pragma unroll
            for (int mt = 0; mt < 4; mt++)
                #pragma unroll
                for (int p = 0; p < 2; p++) {
                    mma_f16(acc[mt][2*p],   a[mt][0], a[mt][1], a[mt][2], a[mt][3],
                            b[p][0], b[p][1]);
                    mma_f16(acc[mt][2*p+1], a[mt][0], a[mt][1], a[mt][2], a[mt][3],
                            b[p][2], b[p][3]);
                }
        }
    };

    constexpr int QTOT = MGRP * 4;
    load_A(0, 0);
    cp_commit();
    load_A(1, 1);
    cp_commit();

    int row0 = lane >> 2;
    int col0 = (lane & 3) * 2;

    for (int q = 0; q < QTOT; ++q) {
        if (q + 1 < QTOT) cp_wait1(); else cp_wait0();
        __syncthreads();                 // stage q%3 visible; compute(q-1) done
        if (q + 2 < QTOT) {
            load_A((q + 2) % 3, q + 2);  // target != read stage, barrier-safe
            cp_commit();
        }
        compute(q % 3, q & 3);
        if ((q & 3) == 3) {
            int bm = (m0tile + (q >> 2)) * GBM;
            #pragma unroll
            for (int mt = 0; mt < 4; mt++) {
                #pragma unroll
                for (int half_ = 0; half_ < 2; half_++) {
                    int m = bm + wm + mt * 16 + row0 + half_ * 8;
                    float2 p0 = part[m];
                    float2 p1 = part[M + m];
                    float mu = (p0.x + p1.x) * (1.0f / C);
                    float rs = rsqrtf((p0.y + p1.y) * (1.0f / C) - mu * mu + 1e-5f);
                    #pragma unroll
                    for (int nt = 0; nt < 4; nt++) {
                        int nl = wn + nt * 8 + col0;
                        int n = bn + nl;
                        float v0 = acc[mt][nt][half_ * 2 + 0];
                        float v1 = acc[mt][nt][half_ * 2 + 1];
                        v0 = rs * v0 - rs * mu * s_csum[nl] + s_bias[nl];
                        v1 = rs * v1 - rs * mu * s_csum[nl + 1] + s_bias[nl + 1];
                        if (EPI == 3) { v0 = gelu_exact(v0); v1 = gelu_exact(v1); }
                        if (OUTK == 0 || OUTK == 2)
                            *reinterpret_cast<float2*>(&outf[(size_t)m * NDIM + n]) =
                                make_float2(v0, v1);
                        if (OUTK == 1 || OUTK == 2) {
                            uint32_t h = pack2(v0, v1);
                            *reinterpret_cast<uint32_t*>(&outh[(size_t)m * NDIM + n]) = h;
                        }
                        acc[mt][nt][half_ * 2 + 0] = 0.f;
                        acc[mt][nt][half_ * 2 + 1] = 0.f;
                    }
                }
            }
        }
    }
}

// ---------------------------------------------------------------------------
// Conv GEMM. zsel=0: conv1 -> half x1 + stats | zsel=1: conv3 -> fp32 x3
// ---------------------------------------------------------------------------
__global__ void __launch_bounds__(256, 2)
convk(const __half* __restrict__ Aq, const __half* __restrict__ Akv,
      const __half* __restrict__ W1, const __half* __restrict__ W3,
      const float* __restrict__ b1, const float* __restrict__ b3,
      __half* __restrict__ outh, float* __restrict__ outf,
      float2* __restrict__ part, int zsel) {
    extern __shared__ char sm[];
    __shared__ float s_bias[GBN];

    int z = zsel;
    const __half* Ah = z ? Akv : Aq;
    const __half* Bw = z ? W3 : W1;
    const float* bias = z ? b3 : b1;

    int tid = threadIdx.x;
    int lane = tid & 31;
    int warp = tid >> 5;
    int bm = blockIdx.x * GBM;
    int bn = blockIdx.y * GBN;
    int wm = (warp & 1) * 64;
    int wn = (warp >> 1) * 32;

    if (tid < GBN) s_bias[tid] = bias[bn + tid];

    int p_row = tid >> 1;
    int p_ch  = (tid & 1) * 4;
    int gm = bm + p_row;
    int bb = gm / HW;
    int rr0 = gm - bb * HW;
    int hh = rr0 / Wc;
    int ww = rr0 - hh * Wc;

    uint32_t sbase = smem_u32(sm);

    auto load_stage = [&](int stg, int tap) {
        uint32_t sA = sbase + stg * STGB;
        uint32_t sB = sA + ASZB;
        int dr = tap / 3 - 1, dc = tap % 3 - 1;
        int rr = hh + dr, cc = ww + dc;
        bool valid = (rr >= 0 && rr < Hc && cc >= 0 && cc < Wc);
        int sz = valid ? 16 : 0;
        const __half* srcrow = Ah +
            ((size_t)bb * HW + (valid ? rr * Wc + cc : 0)) * CIN;
        #pragma unroll
        for (int j = 0; j < 4; j++) {
            int ch = p_ch + j;
            cp16z(sA + p_row * ASTB + ch * 16, srcrow + ch * 8, sz);
        }
        #pragma unroll
        for (int j = 0; j < 4; j++) {
            int ch = p_ch + j;
            cp16(sB + p_row * ASTB + ch * 16,
                 Bw + (size_t)(bn + p_row) * KC + tap * 64 + ch * 8);
        }
    };

    uint32_t aA[4], bA[2];
    {
        int r = (lane & 7) + ((lane >> 3) & 1) * 8;
        int c16 = ((lane >> 4) & 1) * 16;
        #pragma unroll
        for (int mt = 0; mt < 4; mt++)
            aA[mt] = sbase + (wm + mt * 16 + r) * ASTB + c16;
        int rb = (lane & 7) + ((lane >> 4) & 1) * 8;
        int cb16 = ((lane >> 3) & 1) * 16;
        #pragma unroll
        for (int p = 0; p < 2; p++)
            bA[p] = sbase + ASZB + (wn + p * 16 + rb) * ASTB + cb16;
    }

    float acc[4][4][4];
    #pragma unroll
    for (int mt = 0; mt < 4; mt++)
        #pragma unroll
        for (int nt = 0; nt < 4; nt++)
            #pragma unroll
            for (int r = 0; r < 4; r++) acc[mt][nt][r] = 0.f;

    auto compute = [&](int buf) {
        uint32_t off = buf * STGB;
        #pragma unroll
        for (int kg = 0; kg < 4; kg++) {
            uint32_t a[4][4], b[2][4];
            #pragma unroll
            for (int mt = 0; mt < 4; mt++)
                ldsm4(aA[mt] + off + kg * 32, a[mt][0], a[mt][1], a[mt][2], a[mt][3]);
            #pragma unroll
            for (int p = 0; p < 2; p++)
                ldsm4(bA[p] + off + kg * 32, b[p][0], b[p][1], b[p][2], b[p][3]);
            #pragma unroll
            for (int mt = 0; mt < 4; mt++)
                #pragma unroll
                for (int p = 0; p < 2; p++) {
                    mma_f16(acc[mt][2*p],   a[mt][0], a[mt][1], a[mt][2], a[mt][3],
                            b[p][0], b[p][1]);
                    mma_f16(acc[mt][2*p+1], a[mt][0], a[mt][1], a[mt][2], a[mt][3],
                            b[p][2], b[p][3]);
                }
        }
    };

    constexpr int NIT = 9;
    load_stage(0, 0);
    cp_commit();
    load_stage(1, 1);
    cp_commit();

    for (int it = 0; it < NIT; ++it) {
        if (it + 1 < NIT) cp_wait1(); else cp_wait0();
        __syncthreads();
        compute(it % NSTG);
        if (it + 2 < NIT) {
            load_stage((it + 2) % NSTG, it + 2);
            cp_commit();
        }
    }

    int row0 = lane >> 2;
    int col0 = (lane & 3) * 2;
    float* sp = reinterpret_cast<float*>(sm);
    if (z == 0) __syncthreads();

    #pragma unroll
    for (int mt = 0; mt < 4; mt++) {
        #pragma unroll
        for (int half_ = 0; half_ < 2; half_++) {
            int ml = wm + mt * 16 + row0 + half_ * 8;
            int m = bm + ml;
            float rsum = 0.f, rsq = 0.f;
            #pragma unroll
            for (int nt = 0; nt < 4; nt++) {
                int nl = wn + nt * 8 + col0;
                int n = bn + nl;
                float v0 = acc[mt][nt][half_ * 2 + 0] + s_bias[nl];
                float v1 = acc[mt][nt][half_ * 2 + 1] + s_bias[nl + 1];
                if (z == 0) {
                    __half2 hv = __floats2half2_rn(v0, v1);
                    float2 f = __half22float2(hv);
                    rsum += f.x + f.y;
                    rsq += f.x * f.x + f.y * f.y;
                    *reinterpret_cast<uint32_t*>(&outh[(size_t)m * C + n]) =
                        *reinterpret_cast<uint32_t*>(&hv);
                } else {
                    *reinterpret_cast<float2*>(&outf[(size_t)m * C + n]) =
                        make_float2(v0, v1);
                }
            }
            if (z == 0) cta_row_stats(sp, lane, warp, rsum, rsq, ml);
        }
    }
    if (z == 0) {
        __syncthreads();
        if (tid < GBM) {
            float s = sp[tid * 8 + 0] + sp[tid * 8 + 2] + sp[tid * 8 + 4] + sp[tid * 8 + 6];
            float q = sp[tid * 8 + 1] + sp[tid * 8 + 3] + sp[tid * 8 + 5] + sp[tid * 8 + 7];
            part[(size_t)blockIdx.y * M + bm + tid] = make_float2(s, q);
        }
    }
}

// ---------------- 3x3 neighborhood attention ----------------
__global__ void __launch_bounds__(64)
nat_attn(const float* __restrict__ rpb) {
    __shared__ float ks[100 * 33];
    __shared__ float vs[100 * 33];

    int ti = blockIdx.x / 14;
    int tj = blockIdx.x % 14;
    int head = blockIdx.y;
    int b = blockIdx.z;
    int tid = threadIdx.x;
    int r0 = ti * 8 - 1;
    int c0 = tj * 8 - 1;

    for (int idx = tid; idx < 100 * 4; idx += 64) {
        int pos = idx >> 2;
        int d0 = (idx & 3) * 8;
        int rr = pos / 10, cc = pos % 10;
        int gi = r0 + rr, gj = c0 + cc;
        float kf[8] = {0,0,0,0,0,0,0,0}, vf[8] = {0,0,0,0,0,0,0,0};
        if (gi >= 0 && gi < Hc && gj >= 0 && gj < Wc) {
            size_t base = (size_t)(b * HW + gi * Wc + gj) * (3 * C) + head * HD + d0;
            uint4 ku = *reinterpret_cast<const uint4*>(g_qkv + base + C);
            uint4 vu = *reinterpret_cast<const uint4*>(g_qkv + base + 2 * C);
            const __half2* kh = reinterpret_cast<const __half2*>(&ku);
            const __half2* vh = reinterpret_cast<const __half2*>(&vu);
            #pragma unroll
            for (int v = 0; v < 4; v++) {
                float2 f = __half22float2(kh[v]);
                kf[v*2] = f.x; kf[v*2+1] = f.y;
                f = __half22float2(vh[v]);
                vf[v*2] = f.x; vf[v*2+1] = f.y;
            }
        }
        float* kp = ks + pos * 33 + d0;
        float* vp = vs + pos * 33 + d0;
        #pragma unroll
        for (int v = 0; v < 8; v++) { kp[v] = kf[v]; vp[v] = vf[v]; }
    }
    __syncthreads();

    int li = tid >> 3, lj = tid & 7;
    int i = ti * 8 + li;
    int j = tj * 8 + lj;
    int si = min(max(i - 1, 0), Hc - 3);
    int sj = min(max(j - 1, 0), Wc - 3);
    int pi = i - si;
    int pj = j - sj;
    int pbase = (si - r0) * 10 + (sj - c0);

    size_t mq = (size_t)(b * HW + i * Wc + j) * (3 * C) + head * HD;
    float q[HD];
    #pragma unroll
    for (int d = 0; d < HD; d += 8) {
        uint4 qu = *reinterpret_cast<const uint4*>(g_qkv + mq + d);
        const __half2* qh = reinterpret_cast<const __half2*>(&qu);
        #pragma unroll
        for (int v = 0; v < 4; v++) {
            float2 f = __half22float2(qh[v]);
            q[d + v*2] = f.x; q[d + v*2 + 1] = f.y;
        }
    }

    const float* rp = rpb + head * 25;
    float logits[9];
    #pragma unroll
    for (int a = 0; a < 3; a++)
        #pragma unroll
        for (int c = 0; c < 3; c++) {
            const float* kk = ks + (pbase + a * 10 + c) * 33;
            float s = 0.f;
            #pragma unroll
            for (int d = 0; d < HD; d++) s += q[d] * kk[d];
            logits[a * 3 + c] = s + rp[(a - pi + 2) * 5 + (c - pj + 2)];
        }

    float mx = logits[0];
    #pragma unroll
    for (int n = 1; n < 9; n++) mx = fmaxf(mx, logits[n]);
    float wsum = 0.f, wgt[9];
    #pragma unroll
    for (int n = 0; n < 9; n++) { wgt[n] = expf(logits[n] - mx); wsum += wgt[n]; }
    float inv = 1.0f / wsum;

    float o[HD];
    #pragma unroll
    for (int d = 0; d < HD; d++) o[d] = 0.f;
    #pragma unroll
    for (int n = 0; n < 9; n++) {
        float wn = wgt[n] * inv;
        const float* vv = vs + (pbase + (n / 3) * 10 + (n % 3)) * 33;
        #pragma unroll
        for (int d = 0; d < HD; d++) o[d] += wn * vv[d];
    }

    size_t mo = (size_t)(b * HW + i * Wc + j) * C + head * HD;
    #pragma unroll
    for (int d = 0; d < HD; d += 8) {
        uint4 u;
        u.x = pack2(o[d+0], o[d+1]);
        u.y = pack2(o[d+2], o[d+3]);
        u.z = pack2(o[d+4], o[d+5]);
        u.w = pack2(o[d+6], o[d+7]);
        *reinterpret_cast<uint4*>(g_attn + mo + d) = u;
    }
}

// ---------------- launch ----------------
extern "C" void kernel_launch(void* const* d_in, const int* in_sizes, int n_in,
                              void* d_out, int out_size) {
    const float* xq      = (const float*)d_in[0];
    const float* xkv     = (const float*)d_in[1];
    const float* conv1_w = (const float*)d_in[2];
    const float* conv1_b = (const float*)d_in[3];
    const float* conv3_w = (const float*)d_in[4];
    const float* conv3_b = (const float*)d_in[5];
    const float* ln1_w   = (const float*)d_in[6];
    const float* ln1_b   = (const float*)d_in[7];
    const float* ln10_w  = (const float*)d_in[8];
    const float* ln10_b  = (const float*)d_in[9];
    const float* ln3_w   = (const float*)d_in[10];
    const float* ln3_b   = (const float*)d_in[11];
    const float* wq      = (const float*)d_in[12];
    const float* bq      = (const float*)d_in[13];
    const float* wkv     = (const float*)d_in[14];
    const float* bkv     = (const float*)d_in[15];
    const float* rpb     = (const float*)d_in[16];
    const float* wp      = (const float*)d_in[17];
    const float* bp      = (const float*)d_in[18];
    const float* fc1_w   = (const float*)d_in[19];
    const float* fc1_b   = (const float*)d_in[20];
    const float* fc2_w   = (const float*)d_in[21];
    const float* fc2_b   = (const float*)d_in[22];
    float* out = (float*)d_out;

    float *p_x3, *p_att, *p_bqkv, *p_csq, *p_bfc1, *p_csf;
    float2 *p_part1, *p_part3;
    __half *p_xqh, *p_xkvh, *p_x1, *p_qkv, *p_attn, *p_atth, *p_mlp,
           *p_wt1, *p_wt3, *p_wqkv, *p_wfc1, *p_wpT, *p_fc2T;
    cudaGetSymbolAddress((void**)&p_xqh, g_xqh);
    cudaGetSymbolAddress((void**)&p_xkvh, g_xkvh);
    cudaGetSymbolAddress((void**)&p_x1, g_x1);
    cudaGetSymbolAddress((void**)&p_x3, g_x3);
    cudaGetSymbolAddress((void**)&p_qkv, g_qkv);
    cudaGetSymbolAddress((void**)&p_attn, g_attn);
    cudaGetSymbolAddress((void**)&p_att, g_att);
    cudaGetSymbolAddress((void**)&p_atth, g_atth);
    cudaGetSymbolAddress((void**)&p_mlp, g_mlp);
    cudaGetSymbolAddress((void**)&p_part1, g_part1);
    cudaGetSymbolAddress((void**)&p_part3, g_part3);
    cudaGetSymbolAddress((void**)&p_wt1, g_wt1);
    cudaGetSymbolAddress((void**)&p_wt3, g_wt3);
    cudaGetSymbolAddress((void**)&p_wqkv, g_wqkv);
    cudaGetSymbolAddress((void**)&p_bqkv, g_bqkv);
    cudaGetSymbolAddress((void**)&p_csq, g_csq);
    cudaGetSymbolAddress((void**)&p_wfc1, g_wfc1);
    cudaGetSymbolAddress((void**)&p_bfc1, g_bfc1);
    cudaGetSymbolAddress((void**)&p_csf, g_csf);
    cudaGetSymbolAddress((void**)&p_wpT, g_wpT);
    cudaGetSymbolAddress((void**)&p_fc2T, g_fc2T);

    cudaFuncSetAttribute(convk,                cudaFuncAttributeMaxDynamicSharedMemorySize, DYN_SMEM);
    cudaFuncSetAttribute(gemmr<2,1,3*C,4>,     cudaFuncAttributeMaxDynamicSharedMemorySize, DYN_SMEM_R);
    cudaFuncSetAttribute(gemmr<3,1,2*C,2>,     cudaFuncAttributeMaxDynamicSharedMemorySize, DYN_SMEM_R);
    cudaFuncSetAttribute(gemmk<1,2,1,C,C>,     cudaFuncAttributeMaxDynamicSharedMemorySize, DYN_SMEM);
    cudaFuncSetAttribute(gemmk<4,0,0,2*C,C>,   cudaFuncAttributeMaxDynamicSharedMemorySize, DYN_SMEM);

    static cudaStream_t s2 = nullptr;
    static cudaEvent_t ev0 = nullptr, evP = nullptr, ev3 = nullptr;
    if (s2 == nullptr) {
        cudaStreamCreateWithFlags(&s2, cudaStreamNonBlocking);
        cudaEventCreateWithFlags(&ev0, cudaEventDisableTiming);
        cudaEventCreateWithFlags(&evP, cudaEventDisableTiming);
        cudaEventCreateWithFlags(&ev3, cudaEventDisableTiming);
    }

    // fork point at the very start: side stream runs late weight prep
    cudaEventRecord(ev0, 0);
    cudaStreamWaitEvent(s2, ev0, 0);
    prep_late<<<1280, 256, 0, s2>>>(wp, fc2_w, fc1_w, fc1_b, ln3_w, ln3_b);

    // 1. critical-path prep (conv weights, qkv fold, NHWC)
    prep_crit<<<2064, 256>>>(xq, xkv, conv1_w, conv3_w,
                             wq, bq, wkv, bkv, ln1_w, ln1_b, ln10_w, ln10_b);
    cudaEventRecord(evP, 0);

    // side stream: after crit prep, run conv3 (needs xkvh + wt3)
    cudaStreamWaitEvent(s2, evP, 0);
    convk<<<dim3(M / GBM, C / GBN), 256, DYN_SMEM, s2>>>(
        p_xqh, p_xkvh, p_wt1, p_wt3, conv1_b, conv3_b, p_x1, p_x3, p_part1, 1);
    cudaEventRecord(ev3, s2);

    // 2. conv1 (+ LN1 stats in epilogue)
    convk<<<dim3(M / GBM, C / GBN), 256, DYN_SMEM>>>(
        p_xqh, p_xkvh, p_wt1, p_wt3, conv1_b, conv3_b, p_x1, p_x3, p_part1, 0);

    // 3. qkv projection: B-resident swizzled, single-sync mainloop
    gemmr<2,1,3*C,4><<<dim3(M / GBM / 4, (3 * C) / GBN), 256, DYN_SMEM_R>>>(
        p_x1, p_wqkv, p_bqkv, p_part1, p_csq, nullptr, p_qkv);

    // 4. neighborhood attention
    nat_attn<<<dim3(14 * 14, HEADS, Bn), 64>>>(rpb);

    // join: proj needs x3 (and prep_late outputs, ordered before ev3 on s2)
    cudaStreamWaitEvent(0, ev3, 0);

    // 5. proj + x3 residual (+ LN3 stats in epilogue)
    gemmk<1,2,1,C,C><<<dim3(M / GBM, C / GBN), 256, DYN_SMEM>>>(
        p_attn, p_wpT, bp, p_x3, p_att, p_atth, p_part3);

    // 6. fc1: B-resident swizzled + LN from partials + GELU
    gemmr<3,1,2*C,2><<<dim3(M / GBM / 2, (2 * C) / GBN), 256, DYN_SMEM_R>>>(
        p_atth, p_wfc1, p_bfc1, p_part3, p_csf, nullptr, p_mlp);

    // 7. fc2 + att residual, coalesced NCHW store
    gemmk<4,0,0,2*C,C><<<dim3(M / GBM, C / GBN), 256, DYN_SMEM>>>(
        p_mlp, p_fc2T, fc2_b, p_att, out, nullptr, nullptr);
}